// round 10
// baseline (speedup 1.0000x reference)
#include <cuda_runtime.h>
#include <cuda_fp16.h>
#include <cstdint>

#define BB 64
#define TT 1024
#define HH 256
#define NG 4

typedef unsigned long long ull;

// ---------------- device scratch ----------------
__device__ float g_Aih[256 * 64];            // [k][o], o = g*16+s
__device__ float g_Ahh[256 * 64];            // [k][o]
__device__ float g_Bih[4 * 16 * 256];        // [(g*16+s)][j]
__device__ float g_Bhh[4 * 16 * 256];        // [(g*16+s)][j]
__device__ float g_bias[4 * 256];            // [g][j]
// G in fp16, gate-pair interleaved: g_G2[n*512 + pt*256 + j] = (preact gate pt, preact gate pt+2)
__device__ __half2 g_G2[(size_t)BB * TT * 512];

// ---------------- packed f32x2 helpers ----------------
__device__ __forceinline__ ull ffma2(ull a, ull b, ull c) {
    ull d;
    asm("fma.rn.f32x2 %0, %1, %2, %3;" : "=l"(d) : "l"(a), "l"(b), "l"(c));
    return d;
}
__device__ __forceinline__ ull pack2(float lo, float hi) {
    ull r; asm("mov.b64 %0, {%1,%2};" : "=l"(r) : "f"(lo), "f"(hi)); return r;
}
__device__ __forceinline__ float hsum2(ull v) {
    float lo, hi; asm("mov.b64 {%0,%1}, %2;" : "=f"(lo), "=f"(hi) : "l"(v));
    return lo + hi;
}

// ---------------- fast activations ----------------
__device__ __forceinline__ float ex2f(float x) {
    float r; asm("ex2.approx.f32 %0, %1;" : "=f"(r) : "f"(x)); return r;
}
__device__ __forceinline__ float rcpf(float x) {
    float r; asm("rcp.approx.f32 %0, %1;" : "=f"(r) : "f"(x)); return r;
}
__device__ __forceinline__ float sigmoid_f(float x) {
    return rcpf(1.f + ex2f(-1.4426950408889634f * x));
}
__device__ __forceinline__ float tanh_f(float x) {
    float e = ex2f(2.885390081777927f * x);
    return fmaf(-2.f, rcpf(e + 1.f), 1.f);
}

// ---------------- kernel A: compose rank-16 factors ----------------
__global__ void compose_kernel(const float* __restrict__ ih0, const float* __restrict__ ih1,
                               const float* __restrict__ ih2, const float* __restrict__ ih3,
                               const float* __restrict__ ihb,
                               const float* __restrict__ hh0, const float* __restrict__ hh1,
                               const float* __restrict__ hh2, const float* __restrict__ hh3,
                               const float* __restrict__ hhb) {
    int tid = blockIdx.x * blockDim.x + threadIdx.x;
    int stride = gridDim.x * blockDim.x;
    for (int idx = tid; idx < 4 * 256 * 16; idx += stride) {
        int s = idx & 15;
        int d = (idx >> 4) & 255;
        int g = idx >> 12;
        int m = d >> 4, n = d & 15;
        float a_ih = 0.f, a_hh = 0.f;
        #pragma unroll
        for (int r = 0; r < 16; r++) {
            a_ih += ih0[(g * 16 + m) * 16 + r] * ih1[((g * 16 + r) * 16 + n) * 16 + s];
            a_hh += hh0[(g * 16 + m) * 16 + r] * hh1[((g * 16 + r) * 16 + n) * 16 + s];
        }
        g_Aih[d * 64 + g * 16 + s] = a_ih;
        g_Ahh[d * 64 + g * 16 + s] = a_hh;
    }
    for (int idx = tid; idx < 4 * 16 * 256; idx += stride) {
        int j = idx & 255;
        int s = (idx >> 8) & 15;
        int g = idx >> 12;
        int o = j >> 4, p = j & 15;
        float b_ih = 0.f, b_hh = 0.f;
        #pragma unroll
        for (int t = 0; t < 16; t++) {
            b_ih += ih2[((g * 16 + s) * 16 + o) * 16 + t] * ih3[(g * 16 + t) * 16 + p];
            b_hh += hh2[((g * 16 + s) * 16 + o) * 16 + t] * hh3[(g * 16 + t) * 16 + p];
        }
        g_Bih[(g * 16 + s) * 256 + j] = b_ih;
        g_Bhh[(g * 16 + s) * 256 + j] = b_hh;
    }
    for (int idx = tid; idx < 1024; idx += stride)
        g_bias[idx] = ihb[idx] + hhb[idx];
}

// ---------------- dummy kernel: keeps ncu capture slot on scan_kernel ----------------
__global__ void phase_kernel() {}

// ---------------- kernel B: fused Z + G, 2 rows per iter, fp16 G output ----------------
__global__ __launch_bounds__(256) void zg_kernel(const float* __restrict__ x) {
    __shared__ __align__(16) float xs[2][256];
    __shared__ __align__(16) float zs[2][64];
    int tid = threadIdx.x;

    // ---- phase-A role (z): No=4 blocked, conflict-floor rotated LDS ----
    int w    = tid >> 5;
    int lane = tid & 31;
    int ogl  = lane >> 4;
    int ks   = lane & 15;
    int og   = w * 2 + ogl;            // 0..15, outputs og*4..og*4+3
    int rot  = (ks >> 1) & 3;
    ull wz[32];
    #pragma unroll
    for (int i = 0; i < 4; i++) {
        int cc = (i + rot) & 3;
        int kb = ks * 16 + cc * 4;
        #pragma unroll
        for (int oi = 0; oi < 4; oi++) {
            int o = og * 4 + oi;
            wz[i * 8 + oi * 2]     = pack2(g_Aih[(kb + 0) * 64 + o], g_Aih[(kb + 1) * 64 + o]);
            wz[i * 8 + oi * 2 + 1] = pack2(g_Aih[(kb + 2) * 64 + o], g_Aih[(kb + 3) * 64 + o]);
        }
    }

    // ---- phase-B role (G): gate-pair pt, columns jh*2, jh*2+1 ----
    int pt = tid >> 7;                 // 0..1 (gates pt and pt+2)
    int jh = tid & 127;
    ull wb[32];
    float biasr[4];
    #pragma unroll
    for (int cI = 0; cI < 2; cI++) {
        int j = jh * 2 + cI;
        #pragma unroll
        for (int gg = 0; gg < 2; gg++) {
            int gate = pt + 2 * gg;
            #pragma unroll
            for (int p = 0; p < 8; p++)
                wb[(cI * 2 + gg) * 8 + p] = pack2(g_Bih[(gate * 16 + 2 * p) * 256 + j],
                                                  g_Bih[(gate * 16 + 2 * p + 1) * 256 + j]);
            biasr[cI * 2 + gg] = g_bias[gate * 256 + j];
        }
    }

    int totalP = (BB * TT) / 2;
    int p = blockIdx.x;
    float v0 = x[(size_t)(2 * p) * 256 + tid];
    float v1 = x[(size_t)(2 * p + 1) * 256 + tid];

    for (; p < totalP; p += gridDim.x) {
        __syncthreads();
        xs[0][tid] = v0;
        xs[1][tid] = v1;
        __syncthreads();
        int p2 = p + gridDim.x;
        if (p2 < totalP) {
            v0 = x[(size_t)(2 * p2) * 256 + tid];
            v1 = x[(size_t)(2 * p2 + 1) * 256 + tid];
        }

        // phase A: z rows into zs
        #pragma unroll
        for (int r = 0; r < 2; r++) {
            const ulonglong2* xp = (const ulonglong2*)(xs[r] + ks * 16);
            ull az[8] = {0,0,0,0,0,0,0,0};
            #pragma unroll
            for (int i = 0; i < 4; i++) {
                ulonglong2 v = xp[(i + rot) & 3];
                #pragma unroll
                for (int oi = 0; oi < 4; oi++) {
                    az[2 * oi]     = ffma2(wz[i * 8 + oi * 2],     v.x, az[2 * oi]);
                    az[2 * oi + 1] = ffma2(wz[i * 8 + oi * 2 + 1], v.y, az[2 * oi + 1]);
                }
            }
            float s0 = hsum2(az[0]) + hsum2(az[1]);
            float s1 = hsum2(az[2]) + hsum2(az[3]);
            float s2 = hsum2(az[4]) + hsum2(az[5]);
            float s3 = hsum2(az[6]) + hsum2(az[7]);
            #pragma unroll
            for (int d = 1; d < 16; d <<= 1) {
                s0 += __shfl_xor_sync(0xffffffffu, s0, d);
                s1 += __shfl_xor_sync(0xffffffffu, s1, d);
                s2 += __shfl_xor_sync(0xffffffffu, s2, d);
                s3 += __shfl_xor_sync(0xffffffffu, s3, d);
            }
            if (ks == 0)
                *(float4*)&zs[r][og * 4] = make_float4(s0, s1, s2, s3);
        }
        __syncthreads();

        // phase B: gate preacts -> fp16, both rows
        #pragma unroll
        for (int r = 0; r < 2; r++) {
            const ulonglong2* za = (const ulonglong2*)(zs[r] + pt * 16);
            const ulonglong2* zb = (const ulonglong2*)(zs[r] + (pt + 2) * 16);
            ulonglong2 a0 = za[0], a1 = za[1], a2 = za[2], a3 = za[3];
            ulonglong2 b0 = zb[0], b1 = zb[1], b2 = zb[2], b3 = zb[3];
            float rr[4];
            #pragma unroll
            for (int cI = 0; cI < 2; cI++) {
                ull u = 0ULL, uu = 0ULL, v = 0ULL, vv = 0ULL;
                u  = ffma2(wb[(cI * 2) * 8 + 0], a0.x, u);
                uu = ffma2(wb[(cI * 2) * 8 + 1], a0.y, uu);
                u  = ffma2(wb[(cI * 2) * 8 + 2], a1.x, u);
                uu = ffma2(wb[(cI * 2) * 8 + 3], a1.y, uu);
                u  = ffma2(wb[(cI * 2) * 8 + 4], a2.x, u);
                uu = ffma2(wb[(cI * 2) * 8 + 5], a2.y, uu);
                u  = ffma2(wb[(cI * 2) * 8 + 6], a3.x, u);
                uu = ffma2(wb[(cI * 2) * 8 + 7], a3.y, uu);
                v  = ffma2(wb[(cI * 2 + 1) * 8 + 0], b0.x, v);
                vv = ffma2(wb[(cI * 2 + 1) * 8 + 1], b0.y, vv);
                v  = ffma2(wb[(cI * 2 + 1) * 8 + 2], b1.x, v);
                vv = ffma2(wb[(cI * 2 + 1) * 8 + 3], b1.y, vv);
                v  = ffma2(wb[(cI * 2 + 1) * 8 + 4], b2.x, v);
                vv = ffma2(wb[(cI * 2 + 1) * 8 + 5], b2.y, vv);
                v  = ffma2(wb[(cI * 2 + 1) * 8 + 6], b3.x, v);
                vv = ffma2(wb[(cI * 2 + 1) * 8 + 7], b3.y, vv);
                rr[cI * 2 + 0] = hsum2(u) + hsum2(uu) + biasr[cI * 2 + 0];
                rr[cI * 2 + 1] = hsum2(v) + hsum2(vv) + biasr[cI * 2 + 1];
            }
            __half2 h0 = __floats2half2_rn(rr[0], rr[1]);
            __half2 h1 = __floats2half2_rn(rr[2], rr[3]);
            __half2* dst = g_G2 + (size_t)(2 * p + r) * 512 + pt * 256 + jh * 2;
            dst[0] = h0;
            dst[1] = h1;
        }
    }
}

// ---------------- kernel C: dual-batch scan — 32 CTAs, 2 recurrences per CTA ----------------
__global__ __launch_bounds__(512, 1) void scan_kernel(float* __restrict__ out, int write_hc) {
    __shared__ __align__(16) float hs[2][256];
    __shared__ __align__(16) float zc[2][64];
    __shared__ __align__(16) float gs[2][4][256];

    int tid = threadIdx.x;
    int b0  = blockIdx.x;          // batch A
    int b1  = blockIdx.x + 32;     // batch B

    // ---- stage-1 role: No=2 outputs per thread over a 16-value h chunk ----
    int w    = tid >> 5;
    int lane = tid & 31;
    int ogl  = lane >> 4;
    int ks   = lane & 15;
    int og   = w * 2 + ogl;            // 0..31
    int o0   = og * 2, o1 = og * 2 + 1;
    int rot  = (ks >> 1) & 3;
    ull wa[16];
    #pragma unroll
    for (int i = 0; i < 4; i++) {
        int cc = (i + rot) & 3;
        int kb = ks * 16 + cc * 4;
        wa[4 * i + 0] = pack2(g_Ahh[(kb + 0) * 64 + o0], g_Ahh[(kb + 1) * 64 + o0]);
        wa[4 * i + 1] = pack2(g_Ahh[(kb + 2) * 64 + o0], g_Ahh[(kb + 3) * 64 + o0]);
        wa[4 * i + 2] = pack2(g_Ahh[(kb + 0) * 64 + o1], g_Ahh[(kb + 1) * 64 + o1]);
        wa[4 * i + 3] = pack2(g_Ahh[(kb + 2) * 64 + o1], g_Ahh[(kb + 3) * 64 + o1]);
    }

    // ---- stage-2 role: thread owns (g2, j) and (g2+2, j), both batches ----
    int g2 = tid >> 8;                 // warp-uniform
    int j  = tid & 255;
    ull wb2[16];
    #pragma unroll
    for (int gg = 0; gg < 2; gg++)
        #pragma unroll
        for (int p = 0; p < 8; p++)
            wb2[gg * 8 + p] = pack2(g_Bhh[((g2 + 2 * gg) * 16 + 2 * p) * 256 + j],
                                    g_Bhh[((g2 + 2 * gg) * 16 + 2 * p + 1) * 256 + j]);

    // ---- cell role: half = tid>>8 owns batch 'half', column jc = tid&255 ----
    int half = tid >> 8;
    int jc   = tid & 255;
    float c = 0.f, hfin = 0.f;
    hs[half][jc] = 0.f;

    const __half2* G0 = g_G2 + (size_t)b0 * TT * 512;
    const __half2* G1 = g_G2 + (size_t)b1 * TT * 512;
    __half2 gphA = G0[g2 * 256 + j];   // (gate g2, gate g2+2), batch A, t=0
    __half2 gphB = G1[g2 * 256 + j];
    float* outb0 = out + (size_t)b0 * TT * HH;
    float* outb1 = out + (size_t)b1 * TT * HH;
    __syncthreads();

    for (int t = 0; t < TT; t++) {
        // ---- stage 1: both batches, interleaved for ILP ----
        {
            const ulonglong2* hpA = (const ulonglong2*)(hs[0] + ks * 16);
            const ulonglong2* hpB = (const ulonglong2*)(hs[1] + ks * 16);
            ull a0 = 0ULL, a1 = 0ULL, a2 = 0ULL, a3 = 0ULL;
            ull c0 = 0ULL, c1 = 0ULL, c2 = 0ULL, c3 = 0ULL;
            #pragma unroll
            for (int i = 0; i < 4; i++) {
                ulonglong2 vA = hpA[(i + rot) & 3];
                ulonglong2 vB = hpB[(i + rot) & 3];
                a0 = ffma2(wa[4 * i + 0], vA.x, a0);
                c0 = ffma2(wa[4 * i + 0], vB.x, c0);
                a1 = ffma2(wa[4 * i + 1], vA.y, a1);
                c1 = ffma2(wa[4 * i + 1], vB.y, c1);
                a2 = ffma2(wa[4 * i + 2], vA.x, a2);
                c2 = ffma2(wa[4 * i + 2], vB.x, c2);
                a3 = ffma2(wa[4 * i + 3], vA.y, a3);
                c3 = ffma2(wa[4 * i + 3], vB.y, c3);
            }
            float sA0 = hsum2(a0) + hsum2(a1);
            float sA1 = hsum2(a2) + hsum2(a3);
            float sB0 = hsum2(c0) + hsum2(c1);
            float sB1 = hsum2(c2) + hsum2(c3);
            #pragma unroll
            for (int d = 1; d < 16; d <<= 1) {
                sA0 += __shfl_xor_sync(0xffffffffu, sA0, d);
                sA1 += __shfl_xor_sync(0xffffffffu, sA1, d);
                sB0 += __shfl_xor_sync(0xffffffffu, sB0, d);
                sB1 += __shfl_xor_sync(0xffffffffu, sB1, d);
            }
            if (ks == 0) {
                zc[0][o0] = sA0; zc[0][o1] = sA1;
                zc[1][o0] = sB0; zc[1][o1] = sB1;
            }
        }
        __syncthreads();   // BAR1: zc ready (both batches)

        // ---- stage 2 + activations: both batches ----
        {
            __half2 gnA = gphA, gnB = gphB;
            if (t < TT - 1) {
                gnA = G0[(size_t)(t + 1) * 512 + g2 * 256 + j];
                gnB = G1[(size_t)(t + 1) * 512 + g2 * 256 + j];
            }
            #pragma unroll
            for (int r = 0; r < 2; r++) {
                float2 gf = __half22float2(r == 0 ? gphA : gphB);
                const ulonglong2* zp = (const ulonglong2*)(zc[r] + g2 * 16);
                const ulonglong2* zq = (const ulonglong2*)(zc[r] + (g2 + 2) * 16);
                ulonglong2 u0 = zp[0], u1 = zp[1], u2 = zp[2], u3 = zp[3];
                ulonglong2 w0 = zq[0], w1 = zq[1], w2 = zq[2], w3 = zq[3];
                ull a = 0ULL, aa = 0ULL, bq = 0ULL, bb = 0ULL;
                a  = ffma2(wb2[0],  u0.x, a);  aa = ffma2(wb2[1],  u0.y, aa);
                a  = ffma2(wb2[2],  u1.x, a);  aa = ffma2(wb2[3],  u1.y, aa);
                a  = ffma2(wb2[4],  u2.x, a);  aa = ffma2(wb2[5],  u2.y, aa);
                a  = ffma2(wb2[6],  u3.x, a);  aa = ffma2(wb2[7],  u3.y, aa);
                bq = ffma2(wb2[8],  w0.x, bq); bb = ffma2(wb2[9],  w0.y, bb);
                bq = ffma2(wb2[10], w1.x, bq); bb = ffma2(wb2[11], w1.y, bb);
                bq = ffma2(wb2[12], w2.x, bq); bb = ffma2(wb2[13], w2.y, bb);
                bq = ffma2(wb2[14], w3.x, bq); bb = ffma2(wb2[15], w3.y, bb);
                float v0 = hsum2(a)  + hsum2(aa) + gf.x;
                float v1 = hsum2(bq) + hsum2(bb) + gf.y;
                gs[r][g2][j] = sigmoid_f(v0);
                gs[r][g2 + 2][j] = (g2 == 0) ? tanh_f(v1) : sigmoid_f(v1);
            }
            gphA = gnA; gphB = gnB;
        }
        __syncthreads();   // BAR2: activated gates ready

        // ---- cell: each thread-half updates its own batch's column ----
        {
            float i_ = gs[half][0][jc];
            float f_ = gs[half][1][jc];
            float g_ = gs[half][2][jc];
            float o_ = gs[half][3][jc];
            c = f_ * c + i_ * g_;
            float h = o_ * tanh_f(c);
            hfin = h;
            hs[half][jc] = h;
            (half == 0 ? outb0 : outb1)[(size_t)t * HH + jc] = h;
        }
        __syncthreads();   // BAR3: hs ready for next stage 1
    }

    if (write_hc) {
        int bb = (half == 0) ? b0 : b1;
        out[(size_t)BB * TT * HH + bb * HH + jc]           = hfin;
        out[(size_t)BB * TT * HH + BB * HH + bb * HH + jc] = c;
    }
}

// ---------------- launch ----------------
extern "C" void kernel_launch(void* const* d_in, const int* in_sizes, int n_in,
                              void* d_out, int out_size) {
    const float* x   = (const float*)d_in[0];
    const float* ih0 = (const float*)d_in[1];
    const float* ih1 = (const float*)d_in[2];
    const float* ih2 = (const float*)d_in[3];
    const float* ih3 = (const float*)d_in[4];
    const float* ihb = (const float*)d_in[5];
    const float* hh0 = (const float*)d_in[6];
    const float* hh1 = (const float*)d_in[7];
    const float* hh2 = (const float*)d_in[8];
    const float* hh3 = (const float*)d_in[9];
    const float* hhb = (const float*)d_in[10];

    compose_kernel<<<64, 256>>>(ih0, ih1, ih2, ih3, ihb, hh0, hh1, hh2, hh3, hhb);
    phase_kernel<<<1, 32>>>();   // keeps scan_kernel in ncu's capture slot
    zg_kernel<<<888, 256>>>(x);

    long long need = (long long)BB * TT * HH + 2LL * BB * HH;
    int whc = ((long long)out_size >= need) ? 1 : 0;
    scan_kernel<<<32, 512>>>((float*)d_out, whc);
}

// round 11
// speedup vs baseline: 1.3507x; 1.3507x over previous
#include <cuda_runtime.h>
#include <cuda_fp16.h>
#include <cstdint>

#define BB 64
#define TT 1024
#define HH 256
#define NG 4

typedef unsigned long long ull;

// ---------------- device scratch ----------------
__device__ float g_Aih[256 * 64];            // [k][o], o = g*16+s
__device__ float g_Ahh[256 * 64];            // [k][o]
__device__ float g_Bih[4 * 16 * 256];        // [(g*16+s)][j]
__device__ float g_Bhh[4 * 16 * 256];        // [(g*16+s)][j]
__device__ float g_bias[4 * 256];            // [g][j]
// G in fp16, gate-pair interleaved: g_G2[n*512 + pt*256 + j] = (preact gate pt, preact gate pt+2)
__device__ __half2 g_G2[(size_t)BB * TT * 512];

// ---------------- packed f32x2 helpers ----------------
__device__ __forceinline__ ull ffma2(ull a, ull b, ull c) {
    ull d;
    asm("fma.rn.f32x2 %0, %1, %2, %3;" : "=l"(d) : "l"(a), "l"(b), "l"(c));
    return d;
}
__device__ __forceinline__ ull pack2(float lo, float hi) {
    ull r; asm("mov.b64 %0, {%1,%2};" : "=l"(r) : "f"(lo), "f"(hi)); return r;
}
__device__ __forceinline__ float hsum2(ull v) {
    float lo, hi; asm("mov.b64 {%0,%1}, %2;" : "=f"(lo), "=f"(hi) : "l"(v));
    return lo + hi;
}

// ---------------- fast activations ----------------
__device__ __forceinline__ float ex2f(float x) {
    float r; asm("ex2.approx.f32 %0, %1;" : "=f"(r) : "f"(x)); return r;
}
__device__ __forceinline__ float rcpf(float x) {
    float r; asm("rcp.approx.f32 %0, %1;" : "=f"(r) : "f"(x)); return r;
}
__device__ __forceinline__ float sigmoid_f(float x) {
    return rcpf(1.f + ex2f(-1.4426950408889634f * x));
}
__device__ __forceinline__ float tanh_f(float x) {
    float e = ex2f(2.885390081777927f * x);
    return fmaf(-2.f, rcpf(e + 1.f), 1.f);
}

// ---------------- kernel A: compose rank-16 factors ----------------
__global__ void compose_kernel(const float* __restrict__ ih0, const float* __restrict__ ih1,
                               const float* __restrict__ ih2, const float* __restrict__ ih3,
                               const float* __restrict__ ihb,
                               const float* __restrict__ hh0, const float* __restrict__ hh1,
                               const float* __restrict__ hh2, const float* __restrict__ hh3,
                               const float* __restrict__ hhb) {
    int tid = blockIdx.x * blockDim.x + threadIdx.x;
    int stride = gridDim.x * blockDim.x;
    for (int idx = tid; idx < 4 * 256 * 16; idx += stride) {
        int s = idx & 15;
        int d = (idx >> 4) & 255;
        int g = idx >> 12;
        int m = d >> 4, n = d & 15;
        float a_ih = 0.f, a_hh = 0.f;
        #pragma unroll
        for (int r = 0; r < 16; r++) {
            a_ih += ih0[(g * 16 + m) * 16 + r] * ih1[((g * 16 + r) * 16 + n) * 16 + s];
            a_hh += hh0[(g * 16 + m) * 16 + r] * hh1[((g * 16 + r) * 16 + n) * 16 + s];
        }
        g_Aih[d * 64 + g * 16 + s] = a_ih;
        g_Ahh[d * 64 + g * 16 + s] = a_hh;
    }
    for (int idx = tid; idx < 4 * 16 * 256; idx += stride) {
        int j = idx & 255;
        int s = (idx >> 8) & 15;
        int g = idx >> 12;
        int o = j >> 4, p = j & 15;
        float b_ih = 0.f, b_hh = 0.f;
        #pragma unroll
        for (int t = 0; t < 16; t++) {
            b_ih += ih2[((g * 16 + s) * 16 + o) * 16 + t] * ih3[(g * 16 + t) * 16 + p];
            b_hh += hh2[((g * 16 + s) * 16 + o) * 16 + t] * hh3[(g * 16 + t) * 16 + p];
        }
        g_Bih[(g * 16 + s) * 256 + j] = b_ih;
        g_Bhh[(g * 16 + s) * 256 + j] = b_hh;
    }
    for (int idx = tid; idx < 1024; idx += stride)
        g_bias[idx] = ihb[idx] + hhb[idx];
}

// ---------------- dummy kernel: keeps ncu capture slot on scan_kernel ----------------
__global__ void phase_kernel() {}

// ---------------- kernel B: fused Z + G, 2 rows per iter, fp16 G output ----------------
__global__ __launch_bounds__(256) void zg_kernel(const float* __restrict__ x) {
    __shared__ __align__(16) float xs[2][256];
    __shared__ __align__(16) float zs[2][64];
    int tid = threadIdx.x;

    // ---- phase-A role (z): No=4 blocked, conflict-floor rotated LDS ----
    int w    = tid >> 5;
    int lane = tid & 31;
    int ogl  = lane >> 4;
    int ks   = lane & 15;
    int og   = w * 2 + ogl;            // 0..15, outputs og*4..og*4+3
    int rot  = (ks >> 1) & 3;
    ull wz[32];
    #pragma unroll
    for (int i = 0; i < 4; i++) {
        int cc = (i + rot) & 3;
        int kb = ks * 16 + cc * 4;
        #pragma unroll
        for (int oi = 0; oi < 4; oi++) {
            int o = og * 4 + oi;
            wz[i * 8 + oi * 2]     = pack2(g_Aih[(kb + 0) * 64 + o], g_Aih[(kb + 1) * 64 + o]);
            wz[i * 8 + oi * 2 + 1] = pack2(g_Aih[(kb + 2) * 64 + o], g_Aih[(kb + 3) * 64 + o]);
        }
    }

    // ---- phase-B role (G): gate-pair pt, columns jh*2, jh*2+1 ----
    int pt = tid >> 7;                 // 0..1 (gates pt and pt+2)
    int jh = tid & 127;
    ull wb[32];
    float biasr[4];
    #pragma unroll
    for (int cI = 0; cI < 2; cI++) {
        int j = jh * 2 + cI;
        #pragma unroll
        for (int gg = 0; gg < 2; gg++) {
            int gate = pt + 2 * gg;
            #pragma unroll
            for (int p = 0; p < 8; p++)
                wb[(cI * 2 + gg) * 8 + p] = pack2(g_Bih[(gate * 16 + 2 * p) * 256 + j],
                                                  g_Bih[(gate * 16 + 2 * p + 1) * 256 + j]);
            biasr[cI * 2 + gg] = g_bias[gate * 256 + j];
        }
    }

    int totalP = (BB * TT) / 2;
    int p = blockIdx.x;
    float v0 = x[(size_t)(2 * p) * 256 + tid];
    float v1 = x[(size_t)(2 * p + 1) * 256 + tid];

    for (; p < totalP; p += gridDim.x) {
        __syncthreads();
        xs[0][tid] = v0;
        xs[1][tid] = v1;
        __syncthreads();
        int p2 = p + gridDim.x;
        if (p2 < totalP) {
            v0 = x[(size_t)(2 * p2) * 256 + tid];
            v1 = x[(size_t)(2 * p2 + 1) * 256 + tid];
        }

        // phase A: z rows into zs
        #pragma unroll
        for (int r = 0; r < 2; r++) {
            const ulonglong2* xp = (const ulonglong2*)(xs[r] + ks * 16);
            ull az[8] = {0,0,0,0,0,0,0,0};
            #pragma unroll
            for (int i = 0; i < 4; i++) {
                ulonglong2 v = xp[(i + rot) & 3];
                #pragma unroll
                for (int oi = 0; oi < 4; oi++) {
                    az[2 * oi]     = ffma2(wz[i * 8 + oi * 2],     v.x, az[2 * oi]);
                    az[2 * oi + 1] = ffma2(wz[i * 8 + oi * 2 + 1], v.y, az[2 * oi + 1]);
                }
            }
            float s0 = hsum2(az[0]) + hsum2(az[1]);
            float s1 = hsum2(az[2]) + hsum2(az[3]);
            float s2 = hsum2(az[4]) + hsum2(az[5]);
            float s3 = hsum2(az[6]) + hsum2(az[7]);
            #pragma unroll
            for (int d = 1; d < 16; d <<= 1) {
                s0 += __shfl_xor_sync(0xffffffffu, s0, d);
                s1 += __shfl_xor_sync(0xffffffffu, s1, d);
                s2 += __shfl_xor_sync(0xffffffffu, s2, d);
                s3 += __shfl_xor_sync(0xffffffffu, s3, d);
            }
            if (ks == 0)
                *(float4*)&zs[r][og * 4] = make_float4(s0, s1, s2, s3);
        }
        __syncthreads();

        // phase B: gate preacts -> fp16, both rows
        #pragma unroll
        for (int r = 0; r < 2; r++) {
            const ulonglong2* za = (const ulonglong2*)(zs[r] + pt * 16);
            const ulonglong2* zb = (const ulonglong2*)(zs[r] + (pt + 2) * 16);
            ulonglong2 a0 = za[0], a1 = za[1], a2 = za[2], a3 = za[3];
            ulonglong2 b0 = zb[0], b1 = zb[1], b2 = zb[2], b3 = zb[3];
            float rr[4];
            #pragma unroll
            for (int cI = 0; cI < 2; cI++) {
                ull u = 0ULL, uu = 0ULL, v = 0ULL, vv = 0ULL;
                u  = ffma2(wb[(cI * 2) * 8 + 0], a0.x, u);
                uu = ffma2(wb[(cI * 2) * 8 + 1], a0.y, uu);
                u  = ffma2(wb[(cI * 2) * 8 + 2], a1.x, u);
                uu = ffma2(wb[(cI * 2) * 8 + 3], a1.y, uu);
                u  = ffma2(wb[(cI * 2) * 8 + 4], a2.x, u);
                uu = ffma2(wb[(cI * 2) * 8 + 5], a2.y, uu);
                u  = ffma2(wb[(cI * 2) * 8 + 6], a3.x, u);
                uu = ffma2(wb[(cI * 2) * 8 + 7], a3.y, uu);
                v  = ffma2(wb[(cI * 2 + 1) * 8 + 0], b0.x, v);
                vv = ffma2(wb[(cI * 2 + 1) * 8 + 1], b0.y, vv);
                v  = ffma2(wb[(cI * 2 + 1) * 8 + 2], b1.x, v);
                vv = ffma2(wb[(cI * 2 + 1) * 8 + 3], b1.y, vv);
                v  = ffma2(wb[(cI * 2 + 1) * 8 + 4], b2.x, v);
                vv = ffma2(wb[(cI * 2 + 1) * 8 + 5], b2.y, vv);
                v  = ffma2(wb[(cI * 2 + 1) * 8 + 6], b3.x, v);
                vv = ffma2(wb[(cI * 2 + 1) * 8 + 7], b3.y, vv);
                rr[cI * 2 + 0] = hsum2(u) + hsum2(uu) + biasr[cI * 2 + 0];
                rr[cI * 2 + 1] = hsum2(v) + hsum2(vv) + biasr[cI * 2 + 1];
            }
            __half2 h0 = __floats2half2_rn(rr[0], rr[1]);
            __half2 h1 = __floats2half2_rn(rr[2], rr[3]);
            __half2* dst = g_G2 + (size_t)(2 * p + r) * 512 + pt * 256 + jh * 2;
            dst[0] = h0;
            dst[1] = h1;
        }
    }
}

// ---------------- kernel C: single-batch scan (R9 base), cell fused into half1 ----------------
__global__ __launch_bounds__(512, 1) void scan_kernel(float* __restrict__ out, int write_hc) {
    __shared__ __align__(16) float hs[256];
    __shared__ __align__(16) float zc[64];
    __shared__ __align__(16) float ps[256];      // p = i*g exchange (half0 -> half1)

    int tid = threadIdx.x;
    int b   = blockIdx.x;

    // ---- stage-1 role: No=2 outputs per thread over a 16-value h chunk ----
    int w    = tid >> 5;
    int lane = tid & 31;
    int ogl  = lane >> 4;
    int ks   = lane & 15;
    int og   = w * 2 + ogl;            // 0..31
    int o0   = og * 2, o1 = og * 2 + 1;
    int rot  = (ks >> 1) & 3;
    ull wa[16];
    #pragma unroll
    for (int i = 0; i < 4; i++) {
        int cc = (i + rot) & 3;
        int kb = ks * 16 + cc * 4;
        wa[4 * i + 0] = pack2(g_Ahh[(kb + 0) * 64 + o0], g_Ahh[(kb + 1) * 64 + o0]);
        wa[4 * i + 1] = pack2(g_Ahh[(kb + 2) * 64 + o0], g_Ahh[(kb + 3) * 64 + o0]);
        wa[4 * i + 2] = pack2(g_Ahh[(kb + 0) * 64 + o1], g_Ahh[(kb + 1) * 64 + o1]);
        wa[4 * i + 3] = pack2(g_Ahh[(kb + 2) * 64 + o1], g_Ahh[(kb + 3) * 64 + o1]);
    }

    // ---- stage-2 role: thread owns (g2, j) and (g2+2, j) ----
    // half0 (g2=0): gates 0 (i) and 2 (g)  -> p = sigmoid(i)*tanh(g)
    // half1 (g2=1): gates 1 (f) and 3 (o)  -> keeps f,o in regs, owns c
    int g2 = tid >> 8;                 // warp-uniform
    int j  = tid & 255;
    ull wb2[16];
    #pragma unroll
    for (int gg = 0; gg < 2; gg++)
        #pragma unroll
        for (int p = 0; p < 8; p++)
            wb2[gg * 8 + p] = pack2(g_Bhh[((g2 + 2 * gg) * 16 + 2 * p) * 256 + j],
                                    g_Bhh[((g2 + 2 * gg) * 16 + 2 * p + 1) * 256 + j]);

    float c = 0.f, hfin = 0.f;
    float f_ = 0.f, o_ = 0.f;
    if (tid < 256) hs[tid] = 0.f;
    const __half2* Gb = g_G2 + (size_t)b * TT * 512;
    __half2 gph = Gb[g2 * 256 + j];                    // t=0 prefetch
    const __half2* gsrc = Gb + 512 + g2 * 256 + j;     // running pointer for t+1
    float* optr = out + (size_t)b * TT * HH + j;       // running output pointer (half1)
    __syncthreads();

    for (int t = 0; t < TT; t++) {
        // ---- stage 1 ----
        {
            const ulonglong2* hp = (const ulonglong2*)(hs + ks * 16);
            ull a0 = 0ULL, a1 = 0ULL, a2 = 0ULL, a3 = 0ULL;
            #pragma unroll
            for (int i = 0; i < 4; i++) {
                ulonglong2 v = hp[(i + rot) & 3];
                a0 = ffma2(wa[4 * i + 0], v.x, a0);
                a1 = ffma2(wa[4 * i + 1], v.y, a1);
                a2 = ffma2(wa[4 * i + 2], v.x, a2);
                a3 = ffma2(wa[4 * i + 3], v.y, a3);
            }
            float s0 = hsum2(a0) + hsum2(a1);
            float s1 = hsum2(a2) + hsum2(a3);
            #pragma unroll
            for (int d = 1; d < 16; d <<= 1) {
                s0 += __shfl_xor_sync(0xffffffffu, s0, d);
                s1 += __shfl_xor_sync(0xffffffffu, s1, d);
            }
            if (ks == 0) { zc[o0] = s0; zc[o1] = s1; }
        }
        __syncthreads();   // BAR1: zc ready

        // ---- stage 2 + activations ----
        {
            __half2 ghn = gph;
            if (t < TT - 1) ghn = *gsrc;               // prefetch next G
            gsrc += 512;
            float2 gf = __half22float2(gph);
            const ulonglong2* zp = (const ulonglong2*)(zc + g2 * 16);
            const ulonglong2* zq = (const ulonglong2*)(zc + (g2 + 2) * 16);
            ulonglong2 u0 = zp[0], u1 = zp[1], u2 = zp[2], u3 = zp[3];
            ulonglong2 w0 = zq[0], w1 = zq[1], w2 = zq[2], w3 = zq[3];
            ull a = 0ULL, aa = 0ULL, bq = 0ULL, bb = 0ULL;
            a  = ffma2(wb2[0],  u0.x, a);  aa = ffma2(wb2[1],  u0.y, aa);
            a  = ffma2(wb2[2],  u1.x, a);  aa = ffma2(wb2[3],  u1.y, aa);
            a  = ffma2(wb2[4],  u2.x, a);  aa = ffma2(wb2[5],  u2.y, aa);
            a  = ffma2(wb2[6],  u3.x, a);  aa = ffma2(wb2[7],  u3.y, aa);
            bq = ffma2(wb2[8],  w0.x, bq); bb = ffma2(wb2[9],  w0.y, bb);
            bq = ffma2(wb2[10], w1.x, bq); bb = ffma2(wb2[11], w1.y, bb);
            bq = ffma2(wb2[12], w2.x, bq); bb = ffma2(wb2[13], w2.y, bb);
            bq = ffma2(wb2[14], w3.x, bq); bb = ffma2(wb2[15], w3.y, bb);
            float v0 = hsum2(a)  + hsum2(aa) + gf.x;   // gate g2
            float v1 = hsum2(bq) + hsum2(bb) + gf.y;   // gate g2+2
            if (g2 == 0) {                              // warp-uniform branch
                ps[j] = sigmoid_f(v0) * tanh_f(v1);     // p = i * g
            } else {
                f_ = sigmoid_f(v0);                     // f
                o_ = sigmoid_f(v1);                     // o
            }
            gph = ghn;
        }
        __syncthreads();   // BAR2: ps ready

        // ---- cell: half1 only (half0's prefetch already in flight) ----
        if (g2 == 1) {
            c = fmaf(f_, c, ps[j]);
            float h = o_ * tanh_f(c);
            hfin = h;
            hs[j] = h;
            *optr = h;
        }
        optr += HH;
        __syncthreads();   // BAR3: hs ready for next stage 1
    }

    if (write_hc && g2 == 1) {
        out[(size_t)BB * TT * HH + b * HH + j]           = hfin;
        out[(size_t)BB * TT * HH + BB * HH + b * HH + j] = c;
    }
}

// ---------------- launch ----------------
extern "C" void kernel_launch(void* const* d_in, const int* in_sizes, int n_in,
                              void* d_out, int out_size) {
    const float* x   = (const float*)d_in[0];
    const float* ih0 = (const float*)d_in[1];
    const float* ih1 = (const float*)d_in[2];
    const float* ih2 = (const float*)d_in[3];
    const float* ih3 = (const float*)d_in[4];
    const float* ihb = (const float*)d_in[5];
    const float* hh0 = (const float*)d_in[6];
    const float* hh1 = (const float*)d_in[7];
    const float* hh2 = (const float*)d_in[8];
    const float* hh3 = (const float*)d_in[9];
    const float* hhb = (const float*)d_in[10];

    compose_kernel<<<64, 256>>>(ih0, ih1, ih2, ih3, ihb, hh0, hh1, hh2, hh3, hhb);
    phase_kernel<<<1, 32>>>();   // keeps scan_kernel in ncu's capture slot
    zg_kernel<<<888, 256>>>(x);

    long long need = (long long)BB * TT * HH + 2LL * BB * HH;
    int whc = ((long long)out_size >= need) ? 1 : 0;
    scan_kernel<<<BB, 512>>>((float*)d_out, whc);
}

// round 12
// speedup vs baseline: 1.4440x; 1.0691x over previous
#include <cuda_runtime.h>
#include <cuda_fp16.h>
#include <cstdint>

#define BB 64
#define TT 1024
#define HH 256
#define NG 4

typedef unsigned long long ull;

// ---------------- device scratch ----------------
__device__ float g_Aih[256 * 64];            // [k][o], o = g*16+s
__device__ float g_Ahh[256 * 64];            // [k][o]
__device__ float g_Bih[4 * 16 * 256];        // [(g*16+s)][j]
__device__ float g_Bhh[4 * 16 * 256];        // [(g*16+s)][j]
__device__ float g_bias[4 * 256];            // [g][j]
// G in fp16, gate-pair interleaved: g_G2[n*512 + pt*256 + j] = (preact gate pt, preact gate pt+2)
__device__ __half2 g_G2[(size_t)BB * TT * 512];

// ---------------- packed f32x2 helpers ----------------
__device__ __forceinline__ ull ffma2(ull a, ull b, ull c) {
    ull d;
    asm("fma.rn.f32x2 %0, %1, %2, %3;" : "=l"(d) : "l"(a), "l"(b), "l"(c));
    return d;
}
__device__ __forceinline__ ull pack2(float lo, float hi) {
    ull r; asm("mov.b64 %0, {%1,%2};" : "=l"(r) : "f"(lo), "f"(hi)); return r;
}
__device__ __forceinline__ float hsum2(ull v) {
    float lo, hi; asm("mov.b64 {%0,%1}, %2;" : "=f"(lo), "=f"(hi) : "l"(v));
    return lo + hi;
}

// ---------------- fast activations ----------------
__device__ __forceinline__ float ex2f(float x) {
    float r; asm("ex2.approx.f32 %0, %1;" : "=f"(r) : "f"(x)); return r;
}
__device__ __forceinline__ float rcpf(float x) {
    float r; asm("rcp.approx.f32 %0, %1;" : "=f"(r) : "f"(x)); return r;
}
__device__ __forceinline__ float sigmoid_f(float x) {
    return rcpf(1.f + ex2f(-1.4426950408889634f * x));
}
__device__ __forceinline__ float tanh_f(float x) {
    float e = ex2f(2.885390081777927f * x);
    return fmaf(-2.f, rcpf(e + 1.f), 1.f);
}

// ---------------- kernel A: compose rank-16 factors ----------------
__global__ void compose_kernel(const float* __restrict__ ih0, const float* __restrict__ ih1,
                               const float* __restrict__ ih2, const float* __restrict__ ih3,
                               const float* __restrict__ ihb,
                               const float* __restrict__ hh0, const float* __restrict__ hh1,
                               const float* __restrict__ hh2, const float* __restrict__ hh3,
                               const float* __restrict__ hhb) {
    int tid = blockIdx.x * blockDim.x + threadIdx.x;
    int stride = gridDim.x * blockDim.x;
    for (int idx = tid; idx < 4 * 256 * 16; idx += stride) {
        int s = idx & 15;
        int d = (idx >> 4) & 255;
        int g = idx >> 12;
        int m = d >> 4, n = d & 15;
        float a_ih = 0.f, a_hh = 0.f;
        #pragma unroll
        for (int r = 0; r < 16; r++) {
            a_ih += ih0[(g * 16 + m) * 16 + r] * ih1[((g * 16 + r) * 16 + n) * 16 + s];
            a_hh += hh0[(g * 16 + m) * 16 + r] * hh1[((g * 16 + r) * 16 + n) * 16 + s];
        }
        g_Aih[d * 64 + g * 16 + s] = a_ih;
        g_Ahh[d * 64 + g * 16 + s] = a_hh;
    }
    for (int idx = tid; idx < 4 * 16 * 256; idx += stride) {
        int j = idx & 255;
        int s = (idx >> 8) & 15;
        int g = idx >> 12;
        int o = j >> 4, p = j & 15;
        float b_ih = 0.f, b_hh = 0.f;
        #pragma unroll
        for (int t = 0; t < 16; t++) {
            b_ih += ih2[((g * 16 + s) * 16 + o) * 16 + t] * ih3[(g * 16 + t) * 16 + p];
            b_hh += hh2[((g * 16 + s) * 16 + o) * 16 + t] * hh3[(g * 16 + t) * 16 + p];
        }
        g_Bih[(g * 16 + s) * 256 + j] = b_ih;
        g_Bhh[(g * 16 + s) * 256 + j] = b_hh;
    }
    for (int idx = tid; idx < 1024; idx += stride)
        g_bias[idx] = ihb[idx] + hhb[idx];
}

// ---------------- dummy kernel: keeps ncu capture slot on scan_kernel ----------------
__global__ void phase_kernel() {}

// ---------------- kernel B: fused Z + G, 2 rows per iter, fp16 G output ----------------
__global__ __launch_bounds__(256) void zg_kernel(const float* __restrict__ x) {
    __shared__ __align__(16) float xs[2][256];
    __shared__ __align__(16) float zs[2][64];
    int tid = threadIdx.x;

    // ---- phase-A role (z): No=4 blocked, conflict-floor rotated LDS ----
    int w    = tid >> 5;
    int lane = tid & 31;
    int ogl  = lane >> 4;
    int ks   = lane & 15;
    int og   = w * 2 + ogl;            // 0..15, outputs og*4..og*4+3
    int rot  = (ks >> 1) & 3;
    ull wz[32];
    #pragma unroll
    for (int i = 0; i < 4; i++) {
        int cc = (i + rot) & 3;
        int kb = ks * 16 + cc * 4;
        #pragma unroll
        for (int oi = 0; oi < 4; oi++) {
            int o = og * 4 + oi;
            wz[i * 8 + oi * 2]     = pack2(g_Aih[(kb + 0) * 64 + o], g_Aih[(kb + 1) * 64 + o]);
            wz[i * 8 + oi * 2 + 1] = pack2(g_Aih[(kb + 2) * 64 + o], g_Aih[(kb + 3) * 64 + o]);
        }
    }

    // ---- phase-B role (G): gate-pair pt, columns jh*2, jh*2+1 ----
    int pt = tid >> 7;                 // 0..1 (gates pt and pt+2)
    int jh = tid & 127;
    ull wb[32];
    float biasr[4];
    #pragma unroll
    for (int cI = 0; cI < 2; cI++) {
        int j = jh * 2 + cI;
        #pragma unroll
        for (int gg = 0; gg < 2; gg++) {
            int gate = pt + 2 * gg;
            #pragma unroll
            for (int p = 0; p < 8; p++)
                wb[(cI * 2 + gg) * 8 + p] = pack2(g_Bih[(gate * 16 + 2 * p) * 256 + j],
                                                  g_Bih[(gate * 16 + 2 * p + 1) * 256 + j]);
            biasr[cI * 2 + gg] = g_bias[gate * 256 + j];
        }
    }

    int totalP = (BB * TT) / 2;
    int p = blockIdx.x;
    float v0 = x[(size_t)(2 * p) * 256 + tid];
    float v1 = x[(size_t)(2 * p + 1) * 256 + tid];

    for (; p < totalP; p += gridDim.x) {
        __syncthreads();
        xs[0][tid] = v0;
        xs[1][tid] = v1;
        __syncthreads();
        int p2 = p + gridDim.x;
        if (p2 < totalP) {
            v0 = x[(size_t)(2 * p2) * 256 + tid];
            v1 = x[(size_t)(2 * p2 + 1) * 256 + tid];
        }

        // phase A: z rows into zs
        #pragma unroll
        for (int r = 0; r < 2; r++) {
            const ulonglong2* xp = (const ulonglong2*)(xs[r] + ks * 16);
            ull az[8] = {0,0,0,0,0,0,0,0};
            #pragma unroll
            for (int i = 0; i < 4; i++) {
                ulonglong2 v = xp[(i + rot) & 3];
                #pragma unroll
                for (int oi = 0; oi < 4; oi++) {
                    az[2 * oi]     = ffma2(wz[i * 8 + oi * 2],     v.x, az[2 * oi]);
                    az[2 * oi + 1] = ffma2(wz[i * 8 + oi * 2 + 1], v.y, az[2 * oi + 1]);
                }
            }
            float s0 = hsum2(az[0]) + hsum2(az[1]);
            float s1 = hsum2(az[2]) + hsum2(az[3]);
            float s2 = hsum2(az[4]) + hsum2(az[5]);
            float s3 = hsum2(az[6]) + hsum2(az[7]);
            #pragma unroll
            for (int d = 1; d < 16; d <<= 1) {
                s0 += __shfl_xor_sync(0xffffffffu, s0, d);
                s1 += __shfl_xor_sync(0xffffffffu, s1, d);
                s2 += __shfl_xor_sync(0xffffffffu, s2, d);
                s3 += __shfl_xor_sync(0xffffffffu, s3, d);
            }
            if (ks == 0)
                *(float4*)&zs[r][og * 4] = make_float4(s0, s1, s2, s3);
        }
        __syncthreads();

        // phase B: gate preacts -> fp16, both rows
        #pragma unroll
        for (int r = 0; r < 2; r++) {
            const ulonglong2* za = (const ulonglong2*)(zs[r] + pt * 16);
            const ulonglong2* zb = (const ulonglong2*)(zs[r] + (pt + 2) * 16);
            ulonglong2 a0 = za[0], a1 = za[1], a2 = za[2], a3 = za[3];
            ulonglong2 b0 = zb[0], b1 = zb[1], b2 = zb[2], b3 = zb[3];
            float rr[4];
            #pragma unroll
            for (int cI = 0; cI < 2; cI++) {
                ull u = 0ULL, uu = 0ULL, v = 0ULL, vv = 0ULL;
                u  = ffma2(wb[(cI * 2) * 8 + 0], a0.x, u);
                uu = ffma2(wb[(cI * 2) * 8 + 1], a0.y, uu);
                u  = ffma2(wb[(cI * 2) * 8 + 2], a1.x, u);
                uu = ffma2(wb[(cI * 2) * 8 + 3], a1.y, uu);
                u  = ffma2(wb[(cI * 2) * 8 + 4], a2.x, u);
                uu = ffma2(wb[(cI * 2) * 8 + 5], a2.y, uu);
                u  = ffma2(wb[(cI * 2) * 8 + 6], a3.x, u);
                uu = ffma2(wb[(cI * 2) * 8 + 7], a3.y, uu);
                v  = ffma2(wb[(cI * 2 + 1) * 8 + 0], b0.x, v);
                vv = ffma2(wb[(cI * 2 + 1) * 8 + 1], b0.y, vv);
                v  = ffma2(wb[(cI * 2 + 1) * 8 + 2], b1.x, v);
                vv = ffma2(wb[(cI * 2 + 1) * 8 + 3], b1.y, vv);
                v  = ffma2(wb[(cI * 2 + 1) * 8 + 4], b2.x, v);
                vv = ffma2(wb[(cI * 2 + 1) * 8 + 5], b2.y, vv);
                v  = ffma2(wb[(cI * 2 + 1) * 8 + 6], b3.x, v);
                vv = ffma2(wb[(cI * 2 + 1) * 8 + 7], b3.y, vv);
                rr[cI * 2 + 0] = hsum2(u) + hsum2(uu) + biasr[cI * 2 + 0];
                rr[cI * 2 + 1] = hsum2(v) + hsum2(vv) + biasr[cI * 2 + 1];
            }
            __half2 h0 = __floats2half2_rn(rr[0], rr[1]);
            __half2 h1 = __floats2half2_rn(rr[2], rr[3]);
            __half2* dst = g_G2 + (size_t)(2 * p + r) * 512 + pt * 256 + jh * 2;
            dst[0] = h0;
            dst[1] = h1;
        }
    }
}

// ---------------- kernel C: scan with lane-paired gate exchange, 2 BARs/step ----------------
// Stage-2 mapping: jj = tid>>1 (column), gg = tid&1.
//   gg=0: gates 0 (i) and 2 (g)  -> sends p = sigmoid(i)*tanh(g) via shfl.xor 1
//   gg=1: gates 1 (f) and 3 (o)  -> receives p, owns c, writes hs[jj] and output
__global__ __launch_bounds__(512, 1) void scan_kernel(float* __restrict__ out, int write_hc) {
    __shared__ __align__(16) float hs[256];
    __shared__ __align__(16) float zc[64];

    int tid = threadIdx.x;
    int b   = blockIdx.x;

    // ---- stage-1 role: No=2 outputs per thread over a 16-value h chunk ----
    int w    = tid >> 5;
    int lane = tid & 31;
    int ogl  = lane >> 4;
    int ks   = lane & 15;
    int og   = w * 2 + ogl;            // 0..31
    int o0   = og * 2, o1 = og * 2 + 1;
    int rot  = (ks >> 1) & 3;
    ull wa[16];
    #pragma unroll
    for (int i = 0; i < 4; i++) {
        int cc = (i + rot) & 3;
        int kb = ks * 16 + cc * 4;
        wa[4 * i + 0] = pack2(g_Ahh[(kb + 0) * 64 + o0], g_Ahh[(kb + 1) * 64 + o0]);
        wa[4 * i + 1] = pack2(g_Ahh[(kb + 2) * 64 + o0], g_Ahh[(kb + 3) * 64 + o0]);
        wa[4 * i + 2] = pack2(g_Ahh[(kb + 0) * 64 + o1], g_Ahh[(kb + 1) * 64 + o1]);
        wa[4 * i + 3] = pack2(g_Ahh[(kb + 2) * 64 + o1], g_Ahh[(kb + 3) * 64 + o1]);
    }

    // ---- stage-2 role: lane-paired (jj, gg) ----
    int jj = tid >> 1;
    int gg = tid & 1;
    ull wb2[16];
    #pragma unroll
    for (int g2i = 0; g2i < 2; g2i++)
        #pragma unroll
        for (int p = 0; p < 8; p++)
            wb2[g2i * 8 + p] = pack2(g_Bhh[((gg + 2 * g2i) * 16 + 2 * p) * 256 + jj],
                                     g_Bhh[((gg + 2 * g2i) * 16 + 2 * p + 1) * 256 + jj]);

    // branch-free activation constants for the second gate (gg=0: tanh, gg=1: sigmoid)
    float k2 = gg ? -1.4426950408889634f : 2.885390081777927f;
    float m2 = gg ? 1.f : -2.f;
    float c2 = gg ? 0.f : 1.f;

    float c = 0.f, hfin = 0.f;
    if (tid < 256) hs[tid] = 0.f;
    const __half2* Gb = g_G2 + (size_t)b * TT * 512;
    __half2 gph = Gb[gg * 256 + jj];                   // t=0 prefetch
    const __half2* gsrc = Gb + 512 + gg * 256 + jj;    // running pointer for t+1
    float* optr = out + (size_t)b * TT * HH + jj;      // odd lanes write here
    __syncthreads();

    for (int t = 0; t < TT; t++) {
        // ---- stage 1 ----
        {
            const ulonglong2* hp = (const ulonglong2*)(hs + ks * 16);
            ull a0 = 0ULL, a1 = 0ULL, a2 = 0ULL, a3 = 0ULL;
            #pragma unroll
            for (int i = 0; i < 4; i++) {
                ulonglong2 v = hp[(i + rot) & 3];
                a0 = ffma2(wa[4 * i + 0], v.x, a0);
                a1 = ffma2(wa[4 * i + 1], v.y, a1);
                a2 = ffma2(wa[4 * i + 2], v.x, a2);
                a3 = ffma2(wa[4 * i + 3], v.y, a3);
            }
            float s0 = hsum2(a0) + hsum2(a1);
            float s1 = hsum2(a2) + hsum2(a3);
            #pragma unroll
            for (int d = 1; d < 16; d <<= 1) {
                s0 += __shfl_xor_sync(0xffffffffu, s0, d);
                s1 += __shfl_xor_sync(0xffffffffu, s1, d);
            }
            if (ks == 0) { zc[o0] = s0; zc[o1] = s1; }
        }
        __syncthreads();   // BAR1: zc ready

        // ---- stage 2 + activations + cell (fused, one phase) ----
        {
            __half2 ghn = gph;
            if (t < TT - 1) ghn = *gsrc;               // prefetch next G
            gsrc += 512;
            float2 gf = __half22float2(gph);
            const ulonglong2* zp = (const ulonglong2*)(zc + gg * 16);
            const ulonglong2* zq = (const ulonglong2*)(zc + (gg + 2) * 16);
            ulonglong2 u0 = zp[0], u1 = zp[1], u2 = zp[2], u3 = zp[3];
            ulonglong2 w0 = zq[0], w1 = zq[1], w2 = zq[2], w3 = zq[3];
            ull a = 0ULL, aa = 0ULL, bq = 0ULL, bb = 0ULL;
            a  = ffma2(wb2[0],  u0.x, a);  aa = ffma2(wb2[1],  u0.y, aa);
            a  = ffma2(wb2[2],  u1.x, a);  aa = ffma2(wb2[3],  u1.y, aa);
            a  = ffma2(wb2[4],  u2.x, a);  aa = ffma2(wb2[5],  u2.y, aa);
            a  = ffma2(wb2[6],  u3.x, a);  aa = ffma2(wb2[7],  u3.y, aa);
            bq = ffma2(wb2[8],  w0.x, bq); bb = ffma2(wb2[9],  w0.y, bb);
            bq = ffma2(wb2[10], w1.x, bq); bb = ffma2(wb2[11], w1.y, bb);
            bq = ffma2(wb2[12], w2.x, bq); bb = ffma2(wb2[13], w2.y, bb);
            bq = ffma2(wb2[14], w3.x, bq); bb = ffma2(wb2[15], w3.y, bb);
            float v0 = hsum2(a)  + hsum2(aa) + gf.x;   // gate gg   : i (even) / f (odd)
            float v1 = hsum2(bq) + hsum2(bb) + gf.y;   // gate gg+2 : g (even) / o (odd)

            float act0 = sigmoid_f(v0);                             // i or f
            float act1 = fmaf(m2, rcpf(ex2f(k2 * v1) + 1.f), c2);   // tanh(g) or sigmoid(o)

            // even lane sends p = i*g to its odd partner
            float pv = __shfl_xor_sync(0xffffffffu, act0 * act1, 1);

            if (gg) {                                  // odd lane: cell update for column jj
                c = fmaf(act0, c, pv);                 // c = f*c + i*g
                float h = act1 * tanh_f(c);            // h = o * tanh(c)
                hfin = h;
                hs[jj] = h;
                *optr = h;
            }
            optr += HH;
            gph = ghn;
        }
        __syncthreads();   // BAR2: hs ready for next stage 1
    }

    if (write_hc && gg) {
        out[(size_t)BB * TT * HH + b * HH + jj]           = hfin;
        out[(size_t)BB * TT * HH + BB * HH + b * HH + jj] = c;
    }
}

// ---------------- launch ----------------
extern "C" void kernel_launch(void* const* d_in, const int* in_sizes, int n_in,
                              void* d_out, int out_size) {
    const float* x   = (const float*)d_in[0];
    const float* ih0 = (const float*)d_in[1];
    const float* ih1 = (const float*)d_in[2];
    const float* ih2 = (const float*)d_in[3];
    const float* ih3 = (const float*)d_in[4];
    const float* ihb = (const float*)d_in[5];
    const float* hh0 = (const float*)d_in[6];
    const float* hh1 = (const float*)d_in[7];
    const float* hh2 = (const float*)d_in[8];
    const float* hh3 = (const float*)d_in[9];
    const float* hhb = (const float*)d_in[10];

    compose_kernel<<<64, 256>>>(ih0, ih1, ih2, ih3, ihb, hh0, hh1, hh2, hh3, hhb);
    phase_kernel<<<1, 32>>>();   // keeps scan_kernel in ncu's capture slot
    zg_kernel<<<888, 256>>>(x);

    long long need = (long long)BB * TT * HH + 2LL * BB * HH;
    int whc = ((long long)out_size >= need) ? 1 : 0;
    scan_kernel<<<BB, 512>>>((float*)d_out, whc);
}